// round 2
// baseline (speedup 1.0000x reference)
#include <cuda_runtime.h>
#include <math.h>

#define NN 100000
#define EE 640000

// ---------------- scratch (device globals; no allocation allowed) ----------------
__device__ float g_node_h[(size_t)NN * 128];
__device__ float g_edge_h[(size_t)EE * 128];
__device__ float g_projA[(size_t)NN * 256];   // node_h @ eW1[rows   0:128]
__device__ float g_projB[(size_t)NN * 256];   // node_h @ eW1[rows 128:256]
__device__ float g_hbuf[(size_t)EE * 256];    // edge hidden
__device__ float g_agg[(size_t)NN * 128];
__device__ float g_nh[(size_t)NN * 256];      // node hidden
__device__ float g_qvec[128];
__device__ float g_qc[3 * 256];               // q @ eW1[rows 384:512] + eb1, per layer

// ---------------- small kernels ----------------
__global__ void k_qvec(const float* __restrict__ q, const float* __restrict__ qW,
                       const float* __restrict__ qb) {
    __shared__ float qs[768];
    int t = threadIdx.x;  // 128 threads
    for (int i = t; i < 768; i += 128) qs[i] = q[i];
    __syncthreads();
    float s = qb[t];
    #pragma unroll 8
    for (int k = 0; k < 768; k++) s += qs[k] * qW[k * 128 + t];
    g_qvec[t] = s;
}

__global__ void k_qc(const float* __restrict__ eW1, const float* __restrict__ eb1) {
    __shared__ float qs[128];
    int l = blockIdx.x, t = threadIdx.x;  // 3 blocks x 256 threads
    if (t < 128) qs[t] = g_qvec[t];
    __syncthreads();
    const float* W = eW1 + ((size_t)l * 512 + 384) * 256;
    float s = eb1[l * 256 + t];
    #pragma unroll 8
    for (int k = 0; k < 128; k++) s += qs[k] * W[k * 256 + t];
    g_qc[l * 256 + t] = s;
}

// ---------------- GEMM building blocks ----------------
// Tile: 64 rows x (256 or 128) cols, 256 threads, thread = (tx=tid&15, ty=tid>>4)
// Thread computes 4 rows (ty*4+e) x cols c = g*64 + tx*4 + v.
// A stored transposed in smem: Asm[k*68 + row]  (pitch 68 for bank spread)
// W stored natural in smem:    Wsm[k*COLS + c]

__device__ __forceinline__ void load_w_smem(const float* __restrict__ Wg, float* Wsm, int tid) {
    // 128*256 or 256*128 floats == 8192 float4
    const float4* src = (const float4*)Wg;
    float4* dst = (float4*)Wsm;
    #pragma unroll
    for (int i = 0; i < 32; i++) dst[tid + i * 256] = src[tid + i * 256];
}

__device__ __forceinline__ void load_a_t(const float* __restrict__ src, int rowBase,
                                         int maxRow, int kTotal4 /*32 or 64*/,
                                         int rowPitch /*128 or 256*/, float* Asm, int tid) {
    int e = tid & 63;
    int r = rowBase + e;
    if (r > maxRow) r = maxRow;
    int kc0 = tid >> 6;  // 0..3
    int iters = kTotal4 >> 2;  // kTotal4/4
    for (int i = 0; i < iters; i++) {
        int kc = kc0 + 4 * i;
        float4 v = *(const float4*)(src + (size_t)r * rowPitch + kc * 4);
        Asm[(kc * 4 + 0) * 68 + e] = v.x;
        Asm[(kc * 4 + 1) * 68 + e] = v.y;
        Asm[(kc * 4 + 2) * 68 + e] = v.z;
        Asm[(kc * 4 + 3) * 68 + e] = v.w;
    }
}

__device__ __forceinline__ void core_k128_c256(const float* __restrict__ Asm,
                                               const float* __restrict__ Wsm,
                                               float acc[4][16], int tx, int ty) {
    #pragma unroll 4
    for (int k = 0; k < 128; k++) {
        float4 a  = *(const float4*)(Asm + k * 68 + ty * 4);
        float4 b0 = *(const float4*)(Wsm + k * 256 + tx * 4);
        float4 b1 = *(const float4*)(Wsm + k * 256 + 64 + tx * 4);
        float4 b2 = *(const float4*)(Wsm + k * 256 + 128 + tx * 4);
        float4 b3 = *(const float4*)(Wsm + k * 256 + 192 + tx * 4);
        float av[4] = {a.x, a.y, a.z, a.w};
        float bv[16] = {b0.x, b0.y, b0.z, b0.w, b1.x, b1.y, b1.z, b1.w,
                        b2.x, b2.y, b2.z, b2.w, b3.x, b3.y, b3.z, b3.w};
        #pragma unroll
        for (int e = 0; e < 4; e++)
            #pragma unroll
            for (int j = 0; j < 16; j++) acc[e][j] += av[e] * bv[j];
    }
}

__device__ __forceinline__ void core_k256_c128(const float* __restrict__ Asm,
                                               const float* __restrict__ Wsm,
                                               float acc[4][8], int tx, int ty) {
    #pragma unroll 4
    for (int k = 0; k < 256; k++) {
        float4 a  = *(const float4*)(Asm + k * 68 + ty * 4);
        float4 b0 = *(const float4*)(Wsm + k * 128 + tx * 4);
        float4 b1 = *(const float4*)(Wsm + k * 128 + 64 + tx * 4);
        float av[4] = {a.x, a.y, a.z, a.w};
        float bv[8] = {b0.x, b0.y, b0.z, b0.w, b1.x, b1.y, b1.z, b1.w};
        #pragma unroll
        for (int e = 0; e < 4; e++)
            #pragma unroll
            for (int j = 0; j < 8; j++) acc[e][j] += av[e] * bv[j];
    }
}

// ---------------- per-layer kernels ----------------
// proj: [N,128] @ eW1[rows 0:128] -> projA ; @ eW1[rows 128:256] -> projB
__global__ void __launch_bounds__(256) k_proj(const float* __restrict__ nsrc,
                                              const float* __restrict__ eW1, int layer) {
    extern __shared__ float sm[];
    float* Asm = sm;               // 128*68
    float* Wsm = sm + 128 * 68;    // 128*256
    int tid = threadIdx.x, tx = tid & 15, ty = tid >> 4;
    int rowBase = blockIdx.x * 64;
    load_a_t(nsrc, rowBase, NN - 1, 32, 128, Asm, tid);
    const float* Wl = eW1 + (size_t)layer * 512 * 256;
    for (int half = 0; half < 2; half++) {
        __syncthreads();
        load_w_smem(Wl + (size_t)half * 128 * 256, Wsm, tid);
        __syncthreads();
        float acc[4][16];
        #pragma unroll
        for (int e = 0; e < 4; e++)
            #pragma unroll
            for (int j = 0; j < 16; j++) acc[e][j] = 0.f;
        core_k128_c256(Asm, Wsm, acc, tx, ty);
        float* outb = half ? g_projB : g_projA;
        #pragma unroll
        for (int e = 0; e < 4; e++) {
            int r = rowBase + ty * 4 + e;
            if (r < NN) {
                #pragma unroll
                for (int g = 0; g < 4; g++) {
                    float4 v = make_float4(acc[e][g * 4 + 0], acc[e][g * 4 + 1],
                                           acc[e][g * 4 + 2], acc[e][g * 4 + 3]);
                    *(float4*)(outb + (size_t)r * 256 + g * 64 + tx * 4) = v;
                }
            }
        }
    }
}

// e1: h = relu(edge_h @ Wc + projA[src] + projB[dst] + qc)
__global__ void __launch_bounds__(256) k_e1(const float* __restrict__ ehsrc,
                                            const float* __restrict__ eW1,
                                            const int* __restrict__ eidx, int layer) {
    extern __shared__ float sm[];
    float* Asm = sm;                       // 128*68
    float* Wsm = Asm + 128 * 68;           // 128*256
    float* qsm = Wsm + 128 * 256;          // 256
    int* ssm = (int*)(qsm + 256);          // 64
    int* dsm = ssm + 64;                   // 64
    int tid = threadIdx.x, tx = tid & 15, ty = tid >> 4;
    int rowBase = blockIdx.x * 64;
    if (tid < 64) {
        ssm[tid] = eidx[rowBase + tid];
        dsm[tid] = eidx[EE + rowBase + tid];
    }
    qsm[tid] = g_qc[layer * 256 + tid];
    load_a_t(ehsrc, rowBase, EE - 1, 32, 128, Asm, tid);
    load_w_smem(eW1 + ((size_t)layer * 512 + 256) * 256, Wsm, tid);
    __syncthreads();
    float acc[4][16];
    #pragma unroll
    for (int e = 0; e < 4; e++)
        #pragma unroll
        for (int j = 0; j < 16; j++) acc[e][j] = 0.f;
    core_k128_c256(Asm, Wsm, acc, tx, ty);
    #pragma unroll
    for (int e = 0; e < 4; e++) {
        int er = rowBase + ty * 4 + e;
        int s = ssm[ty * 4 + e], d = dsm[ty * 4 + e];
        #pragma unroll
        for (int g = 0; g < 4; g++) {
            int c = g * 64 + tx * 4;
            float4 pa = *(const float4*)(g_projA + (size_t)s * 256 + c);
            float4 pb = *(const float4*)(g_projB + (size_t)d * 256 + c);
            float4 qv = *(const float4*)(qsm + c);
            float4 o;
            o.x = fmaxf(acc[e][g * 4 + 0] + pa.x + pb.x + qv.x, 0.f);
            o.y = fmaxf(acc[e][g * 4 + 1] + pa.y + pb.y + qv.y, 0.f);
            o.z = fmaxf(acc[e][g * 4 + 2] + pa.z + pb.z + qv.z, 0.f);
            o.w = fmaxf(acc[e][g * 4 + 3] + pa.w + pb.w + qv.w, 0.f);
            *(float4*)(g_hbuf + (size_t)er * 256 + c) = o;
        }
    }
}

// e2: edge_h = h @ eW2 + eb2 ; atomicAdd into agg[src], agg[dst]
__global__ void __launch_bounds__(256) k_e2(const float* __restrict__ eW2l,
                                            const float* __restrict__ eb2l,
                                            const int* __restrict__ eidx) {
    extern __shared__ float sm[];
    float* Asm = sm;                       // 256*68
    float* Wsm = Asm + 256 * 68;           // 256*128
    float* bsm = Wsm + 256 * 128;          // 128
    int* ssm = (int*)(bsm + 128);          // 64
    int* dsm = ssm + 64;                   // 64
    int tid = threadIdx.x, tx = tid & 15, ty = tid >> 4;
    int rowBase = blockIdx.x * 64;
    if (tid < 64) {
        ssm[tid] = eidx[rowBase + tid];
        dsm[tid] = eidx[EE + rowBase + tid];
    }
    if (tid < 128) bsm[tid] = eb2l[tid];
    load_a_t(g_hbuf, rowBase, EE - 1, 64, 256, Asm, tid);
    load_w_smem(eW2l, Wsm, tid);
    __syncthreads();
    float acc[4][8];
    #pragma unroll
    for (int e = 0; e < 4; e++)
        #pragma unroll
        for (int j = 0; j < 8; j++) acc[e][j] = 0.f;
    core_k256_c128(Asm, Wsm, acc, tx, ty);
    #pragma unroll
    for (int e = 0; e < 4; e++) {
        int er = rowBase + ty * 4 + e;
        int s = ssm[ty * 4 + e], d = dsm[ty * 4 + e];
        #pragma unroll
        for (int g = 0; g < 2; g++) {
            int c = g * 64 + tx * 4;
            float v0 = acc[e][g * 4 + 0] + bsm[c + 0];
            float v1 = acc[e][g * 4 + 1] + bsm[c + 1];
            float v2 = acc[e][g * 4 + 2] + bsm[c + 2];
            float v3 = acc[e][g * 4 + 3] + bsm[c + 3];
            *(float4*)(g_edge_h + (size_t)er * 128 + c) = make_float4(v0, v1, v2, v3);
            atomicAdd(&g_agg[(size_t)s * 128 + c + 0], v0);
            atomicAdd(&g_agg[(size_t)s * 128 + c + 1], v1);
            atomicAdd(&g_agg[(size_t)s * 128 + c + 2], v2);
            atomicAdd(&g_agg[(size_t)s * 128 + c + 3], v3);
            atomicAdd(&g_agg[(size_t)d * 128 + c + 0], v0);
            atomicAdd(&g_agg[(size_t)d * 128 + c + 1], v1);
            atomicAdd(&g_agg[(size_t)d * 128 + c + 2], v2);
            atomicAdd(&g_agg[(size_t)d * 128 + c + 3], v3);
        }
    }
}

// n1: nh = relu(node_h @ nW1[0:128] + agg @ nW1[128:256] + nb1)
__global__ void __launch_bounds__(256) k_n1(const float* __restrict__ nsrc,
                                            const float* __restrict__ nW1,
                                            const float* __restrict__ nb1, int layer) {
    extern __shared__ float sm[];
    float* Asm = sm;               // 128*68
    float* Wsm = Asm + 128 * 68;   // 128*256
    float* bsm = Wsm + 128 * 256;  // 256
    int tid = threadIdx.x, tx = tid & 15, ty = tid >> 4;
    int rowBase = blockIdx.x * 64;
    bsm[tid] = nb1[layer * 256 + tid];
    float acc[4][16];
    #pragma unroll
    for (int e = 0; e < 4; e++)
        #pragma unroll
        for (int j = 0; j < 16; j++) acc[e][j] = 0.f;
    for (int phase = 0; phase < 2; phase++) {
        __syncthreads();
        load_a_t(phase ? g_agg : nsrc, rowBase, NN - 1, 32, 128, Asm, tid);
        load_w_smem(nW1 + ((size_t)layer * 256 + phase * 128) * 256, Wsm, tid);
        __syncthreads();
        core_k128_c256(Asm, Wsm, acc, tx, ty);
    }
    #pragma unroll
    for (int e = 0; e < 4; e++) {
        int r = rowBase + ty * 4 + e;
        if (r < NN) {
            #pragma unroll
            for (int g = 0; g < 4; g++) {
                int c = g * 64 + tx * 4;
                float4 v;
                v.x = fmaxf(acc[e][g * 4 + 0] + bsm[c + 0], 0.f);
                v.y = fmaxf(acc[e][g * 4 + 1] + bsm[c + 1], 0.f);
                v.z = fmaxf(acc[e][g * 4 + 2] + bsm[c + 2], 0.f);
                v.w = fmaxf(acc[e][g * 4 + 3] + bsm[c + 3], 0.f);
                *(float4*)(g_nh + (size_t)r * 256 + c) = v;
            }
        }
    }
}

// n2: node_h = nh @ nW2 + nb2
__global__ void __launch_bounds__(256) k_n2(const float* __restrict__ nW2l,
                                            const float* __restrict__ nb2l) {
    extern __shared__ float sm[];
    float* Asm = sm;               // 256*68
    float* Wsm = Asm + 256 * 68;   // 256*128
    float* bsm = Wsm + 256 * 128;  // 128
    int tid = threadIdx.x, tx = tid & 15, ty = tid >> 4;
    int rowBase = blockIdx.x * 64;
    if (tid < 128) bsm[tid] = nb2l[tid];
    load_a_t(g_nh, rowBase, NN - 1, 64, 256, Asm, tid);
    load_w_smem(nW2l, Wsm, tid);
    __syncthreads();
    float acc[4][8];
    #pragma unroll
    for (int e = 0; e < 4; e++)
        #pragma unroll
        for (int j = 0; j < 8; j++) acc[e][j] = 0.f;
    core_k256_c128(Asm, Wsm, acc, tx, ty);
    #pragma unroll
    for (int e = 0; e < 4; e++) {
        int r = rowBase + ty * 4 + e;
        if (r < NN) {
            #pragma unroll
            for (int g = 0; g < 2; g++) {
                int c = g * 64 + tx * 4;
                float4 v = make_float4(acc[e][g * 4 + 0] + bsm[c + 0],
                                       acc[e][g * 4 + 1] + bsm[c + 1],
                                       acc[e][g * 4 + 2] + bsm[c + 2],
                                       acc[e][g * 4 + 3] + bsm[c + 3]);
                *(float4*)(g_node_h + (size_t)r * 128 + c) = v;
            }
        }
    }
}

// scores: out[0:N) = sigmoid(node_h @ nsW + nsb), out[N:N+E) = sigmoid(edge_h @ esW + esb)
__global__ void k_scores(const float* __restrict__ esW, const float* __restrict__ esb,
                         const float* __restrict__ nsW, const float* __restrict__ nsb,
                         float* __restrict__ out) {
    int warp = (blockIdx.x * blockDim.x + threadIdx.x) >> 5;
    int lane = threadIdx.x & 31;
    if (warp >= NN + EE) return;
    const float* row;
    const float* w;
    float b;
    if (warp < NN) { row = g_node_h + (size_t)warp * 128; w = nsW; b = nsb[0]; }
    else           { row = g_edge_h + (size_t)(warp - NN) * 128; w = esW; b = esb[0]; }
    float4 v = ((const float4*)row)[lane];
    float4 wv = ((const float4*)w)[lane];
    float s = v.x * wv.x + v.y * wv.y + v.z * wv.z + v.w * wv.w;
    #pragma unroll
    for (int off = 16; off > 0; off >>= 1) s += __shfl_xor_sync(0xffffffffu, s, off);
    if (lane == 0) out[warp] = 1.f / (1.f + expf(-(s + b)));
}

// ---------------- host ----------------
extern "C" void kernel_launch(void* const* d_in, const int* in_sizes, int n_in,
                              void* d_out, int out_size) {
    const float* node_emb = (const float*)d_in[0];
    const float* rel_emb  = (const float*)d_in[1];
    const float* q_emb    = (const float*)d_in[2];
    const int*   eidx     = (const int*)d_in[3];
    // d_in[4] = edge_type, unused (matches reference)
    const float* qW  = (const float*)d_in[5];
    const float* qb  = (const float*)d_in[6];
    const float* eW1 = (const float*)d_in[7];
    const float* eb1 = (const float*)d_in[8];
    const float* eW2 = (const float*)d_in[9];
    const float* eb2 = (const float*)d_in[10];
    const float* nW1 = (const float*)d_in[11];
    const float* nb1 = (const float*)d_in[12];
    const float* nW2 = (const float*)d_in[13];
    const float* nb2 = (const float*)d_in[14];
    const float* esW = (const float*)d_in[15];
    const float* esb = (const float*)d_in[16];
    const float* nsW = (const float*)d_in[17];
    const float* nsb = (const float*)d_in[18];
    float* out = (float*)d_out;

    const int SMEM_128 = (128 * 68 + 128 * 256 + 512) * 4;               // proj/n1 + slack
    const int SMEM_E1  = (128 * 68 + 128 * 256 + 256) * 4 + 2 * 64 * 4;  // + qc + src/dst
    const int SMEM_256 = (256 * 68 + 256 * 128 + 128) * 4 + 2 * 64 * 4;  // e2/n2
    cudaFuncSetAttribute(k_proj, cudaFuncAttributeMaxDynamicSharedMemorySize, SMEM_128);
    cudaFuncSetAttribute(k_e1,   cudaFuncAttributeMaxDynamicSharedMemorySize, SMEM_E1);
    cudaFuncSetAttribute(k_e2,   cudaFuncAttributeMaxDynamicSharedMemorySize, SMEM_256);
    cudaFuncSetAttribute(k_n1,   cudaFuncAttributeMaxDynamicSharedMemorySize, SMEM_128);
    cudaFuncSetAttribute(k_n2,   cudaFuncAttributeMaxDynamicSharedMemorySize, SMEM_256);

    void* aggPtr = nullptr;
    void* nodeHPtr = nullptr;
    void* edgeHPtr = nullptr;
    cudaGetSymbolAddress(&aggPtr, g_agg);
    cudaGetSymbolAddress(&nodeHPtr, g_node_h);
    cudaGetSymbolAddress(&edgeHPtr, g_edge_h);

    const int NB = (NN + 63) / 64;   // 1563
    const int EB = EE / 64;          // 10000

    k_qvec<<<1, 128>>>(q_emb, qW, qb);
    k_qc<<<3, 256>>>(eW1, eb1);

    const float* nh_src = node_emb;
    const float* eh_src = rel_emb;
    for (int l = 0; l < 3; l++) {
        k_proj<<<NB, 256, SMEM_128>>>(nh_src, eW1, l);
        k_e1<<<EB, 256, SMEM_E1>>>(eh_src, eW1, eidx, l);
        cudaMemsetAsync(aggPtr, 0, (size_t)NN * 128 * sizeof(float));
        k_e2<<<EB, 256, SMEM_256>>>(eW2 + (size_t)l * 256 * 128, eb2 + l * 128, eidx);
        k_n1<<<NB, 256, SMEM_128>>>(nh_src, nW1, nb1, l);
        k_n2<<<NB, 256, SMEM_256>>>(nW2 + (size_t)l * 256 * 128, nb2 + l * 128);
        nh_src = (const float*)nodeHPtr;
        eh_src = (const float*)edgeHPtr;
    }

    int totalWarps = NN + EE;                 // 740000
    int blocks = (totalWarps + 7) / 8;        // 8 warps / 256-thread block
    k_scores<<<blocks, 256>>>(esW, esb, nsW, nsb, out);
}

// round 4
// speedup vs baseline: 1.0032x; 1.0032x over previous
#include <cuda_runtime.h>
#include <math.h>

#define NN 100000
#define EE 640000

// ---------------- scratch (device globals; no allocation allowed) ----------------
__device__ float g_node_h[(size_t)NN * 128];
__device__ float g_edge_h[(size_t)EE * 128];
__device__ float g_projA[(size_t)NN * 256];   // node_h @ eW1[rows   0:128]
__device__ float g_projB[(size_t)NN * 256];   // node_h @ eW1[rows 128:256]
__device__ float g_hbuf[(size_t)EE * 256];    // edge hidden
__device__ float g_agg[(size_t)NN * 128];
__device__ float g_nh[(size_t)NN * 256];      // node hidden
__device__ float g_qvec[128];
__device__ float g_qc[3 * 256];               // q @ eW1[rows 384:512] + eb1, per layer

// ---------------- small kernels ----------------
__global__ void k_qvec(const float* __restrict__ q, const float* __restrict__ qW,
                       const float* __restrict__ qb) {
    __shared__ float qs[768];
    int t = threadIdx.x;  // 128 threads
    for (int i = t; i < 768; i += 128) qs[i] = q[i];
    __syncthreads();
    float s = qb[t];
    #pragma unroll 8
    for (int k = 0; k < 768; k++) s += qs[k] * qW[k * 128 + t];
    g_qvec[t] = s;
}

__global__ void k_qc(const float* __restrict__ eW1, const float* __restrict__ eb1) {
    __shared__ float qs[128];
    int l = blockIdx.x, t = threadIdx.x;  // 3 blocks x 256 threads
    if (t < 128) qs[t] = g_qvec[t];
    __syncthreads();
    const float* W = eW1 + ((size_t)l * 512 + 384) * 256;
    float s = eb1[l * 256 + t];
    #pragma unroll 8
    for (int k = 0; k < 128; k++) s += qs[k] * W[k * 256 + t];
    g_qc[l * 256 + t] = s;
}

// ---------------- GEMM building blocks ----------------
// Tile: 64 rows x (256 or 128) cols, 256 threads, thread = (tx=tid&15, ty=tid>>4)
// Thread computes 4 rows (ty*4+e) x cols c = g*64 + tx*4 + v.
// A stored transposed in smem: Asm[k*68 + row]  (pitch 68 for bank spread)
// W stored natural in smem:    Wsm[k*COLS + c]

__device__ __forceinline__ void load_w_smem(const float* __restrict__ Wg, float* Wsm, int tid) {
    // 128*256 or 256*128 floats == 8192 float4
    const float4* src = (const float4*)Wg;
    float4* dst = (float4*)Wsm;
    #pragma unroll
    for (int i = 0; i < 32; i++) dst[tid + i * 256] = src[tid + i * 256];
}

__device__ __forceinline__ void load_a_t(const float* __restrict__ src, int rowBase,
                                         int maxRow, int kTotal4 /*32 or 64*/,
                                         int rowPitch /*128 or 256*/, float* Asm, int tid) {
    int e = tid & 63;
    int r = rowBase + e;
    if (r > maxRow) r = maxRow;
    int kc0 = tid >> 6;  // 0..3
    int iters = kTotal4 >> 2;  // kTotal4/4
    for (int i = 0; i < iters; i++) {
        int kc = kc0 + 4 * i;
        float4 v = *(const float4*)(src + (size_t)r * rowPitch + kc * 4);
        Asm[(kc * 4 + 0) * 68 + e] = v.x;
        Asm[(kc * 4 + 1) * 68 + e] = v.y;
        Asm[(kc * 4 + 2) * 68 + e] = v.z;
        Asm[(kc * 4 + 3) * 68 + e] = v.w;
    }
}

__device__ __forceinline__ void core_k128_c256(const float* __restrict__ Asm,
                                               const float* __restrict__ Wsm,
                                               float acc[4][16], int tx, int ty) {
    #pragma unroll 4
    for (int k = 0; k < 128; k++) {
        float4 a  = *(const float4*)(Asm + k * 68 + ty * 4);
        float4 b0 = *(const float4*)(Wsm + k * 256 + tx * 4);
        float4 b1 = *(const float4*)(Wsm + k * 256 + 64 + tx * 4);
        float4 b2 = *(const float4*)(Wsm + k * 256 + 128 + tx * 4);
        float4 b3 = *(const float4*)(Wsm + k * 256 + 192 + tx * 4);
        float av[4] = {a.x, a.y, a.z, a.w};
        float bv[16] = {b0.x, b0.y, b0.z, b0.w, b1.x, b1.y, b1.z, b1.w,
                        b2.x, b2.y, b2.z, b2.w, b3.x, b3.y, b3.z, b3.w};
        #pragma unroll
        for (int e = 0; e < 4; e++)
            #pragma unroll
            for (int j = 0; j < 16; j++) acc[e][j] += av[e] * bv[j];
    }
}

__device__ __forceinline__ void core_k256_c128(const float* __restrict__ Asm,
                                               const float* __restrict__ Wsm,
                                               float acc[4][8], int tx, int ty) {
    #pragma unroll 4
    for (int k = 0; k < 256; k++) {
        float4 a  = *(const float4*)(Asm + k * 68 + ty * 4);
        float4 b0 = *(const float4*)(Wsm + k * 128 + tx * 4);
        float4 b1 = *(const float4*)(Wsm + k * 128 + 64 + tx * 4);
        float av[4] = {a.x, a.y, a.z, a.w};
        float bv[8] = {b0.x, b0.y, b0.z, b0.w, b1.x, b1.y, b1.z, b1.w};
        #pragma unroll
        for (int e = 0; e < 4; e++)
            #pragma unroll
            for (int j = 0; j < 8; j++) acc[e][j] += av[e] * bv[j];
    }
}

// ---------------- per-layer kernels ----------------
// proj: [N,128] @ eW1[rows 0:128] -> projA ; @ eW1[rows 128:256] -> projB
__global__ void __launch_bounds__(256) k_proj(const float* __restrict__ nsrc,
                                              const float* __restrict__ eW1, int layer) {
    extern __shared__ float sm[];
    float* Asm = sm;               // 128*68
    float* Wsm = sm + 128 * 68;    // 128*256
    int tid = threadIdx.x, tx = tid & 15, ty = tid >> 4;
    int rowBase = blockIdx.x * 64;
    load_a_t(nsrc, rowBase, NN - 1, 32, 128, Asm, tid);
    const float* Wl = eW1 + (size_t)layer * 512 * 256;
    for (int half = 0; half < 2; half++) {
        __syncthreads();
        load_w_smem(Wl + (size_t)half * 128 * 256, Wsm, tid);
        __syncthreads();
        float acc[4][16];
        #pragma unroll
        for (int e = 0; e < 4; e++)
            #pragma unroll
            for (int j = 0; j < 16; j++) acc[e][j] = 0.f;
        core_k128_c256(Asm, Wsm, acc, tx, ty);
        float* outb = half ? g_projB : g_projA;
        #pragma unroll
        for (int e = 0; e < 4; e++) {
            int r = rowBase + ty * 4 + e;
            if (r < NN) {
                #pragma unroll
                for (int g = 0; g < 4; g++) {
                    float4 v = make_float4(acc[e][g * 4 + 0], acc[e][g * 4 + 1],
                                           acc[e][g * 4 + 2], acc[e][g * 4 + 3]);
                    *(float4*)(outb + (size_t)r * 256 + g * 64 + tx * 4) = v;
                }
            }
        }
    }
}

// e1: h = relu(edge_h @ Wc + projA[src] + projB[dst] + qc)
__global__ void __launch_bounds__(256) k_e1(const float* __restrict__ ehsrc,
                                            const float* __restrict__ eW1,
                                            const int* __restrict__ eidx, int layer) {
    extern __shared__ float sm[];
    float* Asm = sm;                       // 128*68
    float* Wsm = Asm + 128 * 68;           // 128*256
    float* qsm = Wsm + 128 * 256;          // 256
    int* ssm = (int*)(qsm + 256);          // 64
    int* dsm = ssm + 64;                   // 64
    int tid = threadIdx.x, tx = tid & 15, ty = tid >> 4;
    int rowBase = blockIdx.x * 64;
    if (tid < 64) {
        ssm[tid] = eidx[rowBase + tid];
        dsm[tid] = eidx[EE + rowBase + tid];
    }
    qsm[tid] = g_qc[layer * 256 + tid];
    load_a_t(ehsrc, rowBase, EE - 1, 32, 128, Asm, tid);
    load_w_smem(eW1 + ((size_t)layer * 512 + 256) * 256, Wsm, tid);
    __syncthreads();
    float acc[4][16];
    #pragma unroll
    for (int e = 0; e < 4; e++)
        #pragma unroll
        for (int j = 0; j < 16; j++) acc[e][j] = 0.f;
    core_k128_c256(Asm, Wsm, acc, tx, ty);
    #pragma unroll
    for (int e = 0; e < 4; e++) {
        int er = rowBase + ty * 4 + e;
        int s = ssm[ty * 4 + e], d = dsm[ty * 4 + e];
        #pragma unroll
        for (int g = 0; g < 4; g++) {
            int c = g * 64 + tx * 4;
            float4 pa = *(const float4*)(g_projA + (size_t)s * 256 + c);
            float4 pb = *(const float4*)(g_projB + (size_t)d * 256 + c);
            float4 qv = *(const float4*)(qsm + c);
            float4 o;
            o.x = fmaxf(acc[e][g * 4 + 0] + pa.x + pb.x + qv.x, 0.f);
            o.y = fmaxf(acc[e][g * 4 + 1] + pa.y + pb.y + qv.y, 0.f);
            o.z = fmaxf(acc[e][g * 4 + 2] + pa.z + pb.z + qv.z, 0.f);
            o.w = fmaxf(acc[e][g * 4 + 3] + pa.w + pb.w + qv.w, 0.f);
            *(float4*)(g_hbuf + (size_t)er * 256 + c) = o;
        }
    }
}

// e2: edge_h = h @ eW2 + eb2 ; atomicAdd into agg[src], agg[dst]
__global__ void __launch_bounds__(256) k_e2(const float* __restrict__ eW2l,
                                            const float* __restrict__ eb2l,
                                            const int* __restrict__ eidx) {
    extern __shared__ float sm[];
    float* Asm = sm;                       // 256*68
    float* Wsm = Asm + 256 * 68;           // 256*128
    float* bsm = Wsm + 256 * 128;          // 128
    int* ssm = (int*)(bsm + 128);          // 64
    int* dsm = ssm + 64;                   // 64
    int tid = threadIdx.x, tx = tid & 15, ty = tid >> 4;
    int rowBase = blockIdx.x * 64;
    if (tid < 64) {
        ssm[tid] = eidx[rowBase + tid];
        dsm[tid] = eidx[EE + rowBase + tid];
    }
    if (tid < 128) bsm[tid] = eb2l[tid];
    load_a_t(g_hbuf, rowBase, EE - 1, 64, 256, Asm, tid);
    load_w_smem(eW2l, Wsm, tid);
    __syncthreads();
    float acc[4][8];
    #pragma unroll
    for (int e = 0; e < 4; e++)
        #pragma unroll
        for (int j = 0; j < 8; j++) acc[e][j] = 0.f;
    core_k256_c128(Asm, Wsm, acc, tx, ty);
    #pragma unroll
    for (int e = 0; e < 4; e++) {
        int er = rowBase + ty * 4 + e;
        int s = ssm[ty * 4 + e], d = dsm[ty * 4 + e];
        #pragma unroll
        for (int g = 0; g < 2; g++) {
            int c = g * 64 + tx * 4;
            float v0 = acc[e][g * 4 + 0] + bsm[c + 0];
            float v1 = acc[e][g * 4 + 1] + bsm[c + 1];
            float v2 = acc[e][g * 4 + 2] + bsm[c + 2];
            float v3 = acc[e][g * 4 + 3] + bsm[c + 3];
            *(float4*)(g_edge_h + (size_t)er * 128 + c) = make_float4(v0, v1, v2, v3);
            atomicAdd(&g_agg[(size_t)s * 128 + c + 0], v0);
            atomicAdd(&g_agg[(size_t)s * 128 + c + 1], v1);
            atomicAdd(&g_agg[(size_t)s * 128 + c + 2], v2);
            atomicAdd(&g_agg[(size_t)s * 128 + c + 3], v3);
            atomicAdd(&g_agg[(size_t)d * 128 + c + 0], v0);
            atomicAdd(&g_agg[(size_t)d * 128 + c + 1], v1);
            atomicAdd(&g_agg[(size_t)d * 128 + c + 2], v2);
            atomicAdd(&g_agg[(size_t)d * 128 + c + 3], v3);
        }
    }
}

// n1: nh = relu(node_h @ nW1[0:128] + agg @ nW1[128:256] + nb1)
__global__ void __launch_bounds__(256) k_n1(const float* __restrict__ nsrc,
                                            const float* __restrict__ nW1,
                                            const float* __restrict__ nb1, int layer) {
    extern __shared__ float sm[];
    float* Asm = sm;               // 128*68
    float* Wsm = Asm + 128 * 68;   // 128*256
    float* bsm = Wsm + 128 * 256;  // 256
    int tid = threadIdx.x, tx = tid & 15, ty = tid >> 4;
    int rowBase = blockIdx.x * 64;
    bsm[tid] = nb1[layer * 256 + tid];
    float acc[4][16];
    #pragma unroll
    for (int e = 0; e < 4; e++)
        #pragma unroll
        for (int j = 0; j < 16; j++) acc[e][j] = 0.f;
    for (int phase = 0; phase < 2; phase++) {
        __syncthreads();
        load_a_t(phase ? g_agg : nsrc, rowBase, NN - 1, 32, 128, Asm, tid);
        load_w_smem(nW1 + ((size_t)layer * 256 + phase * 128) * 256, Wsm, tid);
        __syncthreads();
        core_k128_c256(Asm, Wsm, acc, tx, ty);
    }
    #pragma unroll
    for (int e = 0; e < 4; e++) {
        int r = rowBase + ty * 4 + e;
        if (r < NN) {
            #pragma unroll
            for (int g = 0; g < 4; g++) {
                int c = g * 64 + tx * 4;
                float4 v;
                v.x = fmaxf(acc[e][g * 4 + 0] + bsm[c + 0], 0.f);
                v.y = fmaxf(acc[e][g * 4 + 1] + bsm[c + 1], 0.f);
                v.z = fmaxf(acc[e][g * 4 + 2] + bsm[c + 2], 0.f);
                v.w = fmaxf(acc[e][g * 4 + 3] + bsm[c + 3], 0.f);
                *(float4*)(g_nh + (size_t)r * 256 + c) = v;
            }
        }
    }
}

// n2: node_h = nh @ nW2 + nb2
__global__ void __launch_bounds__(256) k_n2(const float* __restrict__ nW2l,
                                            const float* __restrict__ nb2l) {
    extern __shared__ float sm[];
    float* Asm = sm;               // 256*68
    float* Wsm = Asm + 256 * 68;   // 256*128
    float* bsm = Wsm + 256 * 128;  // 128
    int tid = threadIdx.x, tx = tid & 15, ty = tid >> 4;
    int rowBase = blockIdx.x * 64;
    if (tid < 128) bsm[tid] = nb2l[tid];
    load_a_t(g_nh, rowBase, NN - 1, 64, 256, Asm, tid);
    load_w_smem(nW2l, Wsm, tid);
    __syncthreads();
    float acc[4][8];
    #pragma unroll
    for (int e = 0; e < 4; e++)
        #pragma unroll
        for (int j = 0; j < 8; j++) acc[e][j] = 0.f;
    core_k256_c128(Asm, Wsm, acc, tx, ty);
    #pragma unroll
    for (int e = 0; e < 4; e++) {
        int r = rowBase + ty * 4 + e;
        if (r < NN) {
            #pragma unroll
            for (int g = 0; g < 2; g++) {
                int c = g * 64 + tx * 4;
                float4 v = make_float4(acc[e][g * 4 + 0] + bsm[c + 0],
                                       acc[e][g * 4 + 1] + bsm[c + 1],
                                       acc[e][g * 4 + 2] + bsm[c + 2],
                                       acc[e][g * 4 + 3] + bsm[c + 3]);
                *(float4*)(g_node_h + (size_t)r * 128 + c) = v;
            }
        }
    }
}

// scores: out[0:N) = sigmoid(node_h @ nsW + nsb), out[N:N+E) = sigmoid(edge_h @ esW + esb)
__global__ void k_scores(const float* __restrict__ esW, const float* __restrict__ esb,
                         const float* __restrict__ nsW, const float* __restrict__ nsb,
                         float* __restrict__ out) {
    int warp = (blockIdx.x * blockDim.x + threadIdx.x) >> 5;
    int lane = threadIdx.x & 31;
    if (warp >= NN + EE) return;
    const float* row;
    const float* w;
    float b;
    if (warp < NN) { row = g_node_h + (size_t)warp * 128; w = nsW; b = nsb[0]; }
    else           { row = g_edge_h + (size_t)(warp - NN) * 128; w = esW; b = esb[0]; }
    float4 v = ((const float4*)row)[lane];
    float4 wv = ((const float4*)w)[lane];
    float s = v.x * wv.x + v.y * wv.y + v.z * wv.z + v.w * wv.w;
    #pragma unroll
    for (int off = 16; off > 0; off >>= 1) s += __shfl_xor_sync(0xffffffffu, s, off);
    if (lane == 0) out[warp] = 1.f / (1.f + expf(-(s + b)));
}

// ---------------- host ----------------
extern "C" void kernel_launch(void* const* d_in, const int* in_sizes, int n_in,
                              void* d_out, int out_size) {
    const float* node_emb = (const float*)d_in[0];
    const float* rel_emb  = (const float*)d_in[1];
    const float* q_emb    = (const float*)d_in[2];
    const int*   eidx     = (const int*)d_in[3];
    // d_in[4] = edge_type, unused (matches reference)
    const float* qW  = (const float*)d_in[5];
    const float* qb  = (const float*)d_in[6];
    const float* eW1 = (const float*)d_in[7];
    const float* eb1 = (const float*)d_in[8];
    const float* eW2 = (const float*)d_in[9];
    const float* eb2 = (const float*)d_in[10];
    const float* nW1 = (const float*)d_in[11];
    const float* nb1 = (const float*)d_in[12];
    const float* nW2 = (const float*)d_in[13];
    const float* nb2 = (const float*)d_in[14];
    const float* esW = (const float*)d_in[15];
    const float* esb = (const float*)d_in[16];
    const float* nsW = (const float*)d_in[17];
    const float* nsb = (const float*)d_in[18];
    float* out = (float*)d_out;

    const int SMEM_128 = (128 * 68 + 128 * 256 + 512) * 4;               // proj/n1 + slack
    const int SMEM_E1  = (128 * 68 + 128 * 256 + 256) * 4 + 2 * 64 * 4;  // + qc + src/dst
    const int SMEM_256 = (256 * 68 + 256 * 128 + 128) * 4 + 2 * 64 * 4;  // e2/n2
    cudaFuncSetAttribute(k_proj, cudaFuncAttributeMaxDynamicSharedMemorySize, SMEM_128);
    cudaFuncSetAttribute(k_e1,   cudaFuncAttributeMaxDynamicSharedMemorySize, SMEM_E1);
    cudaFuncSetAttribute(k_e2,   cudaFuncAttributeMaxDynamicSharedMemorySize, SMEM_256);
    cudaFuncSetAttribute(k_n1,   cudaFuncAttributeMaxDynamicSharedMemorySize, SMEM_128);
    cudaFuncSetAttribute(k_n2,   cudaFuncAttributeMaxDynamicSharedMemorySize, SMEM_256);

    void* aggPtr = nullptr;
    void* nodeHPtr = nullptr;
    void* edgeHPtr = nullptr;
    cudaGetSymbolAddress(&aggPtr, g_agg);
    cudaGetSymbolAddress(&nodeHPtr, g_node_h);
    cudaGetSymbolAddress(&edgeHPtr, g_edge_h);

    const int NB = (NN + 63) / 64;   // 1563
    const int EB = EE / 64;          // 10000

    k_qvec<<<1, 128>>>(q_emb, qW, qb);
    k_qc<<<3, 256>>>(eW1, eb1);

    const float* nh_src = node_emb;
    const float* eh_src = rel_emb;
    for (int l = 0; l < 3; l++) {
        k_proj<<<NB, 256, SMEM_128>>>(nh_src, eW1, l);
        k_e1<<<EB, 256, SMEM_E1>>>(eh_src, eW1, eidx, l);
        cudaMemsetAsync(aggPtr, 0, (size_t)NN * 128 * sizeof(float));
        k_e2<<<EB, 256, SMEM_256>>>(eW2 + (size_t)l * 256 * 128, eb2 + l * 128, eidx);
        k_n1<<<NB, 256, SMEM_128>>>(nh_src, nW1, nb1, l);
        k_n2<<<NB, 256, SMEM_256>>>(nW2 + (size_t)l * 256 * 128, nb2 + l * 128);
        nh_src = (const float*)nodeHPtr;
        eh_src = (const float*)edgeHPtr;
    }

    int totalWarps = NN + EE;                 // 740000
    int blocks = (totalWarps + 7) / 8;        // 8 warps / 256-thread block
    k_scores<<<blocks, 256>>>(esW, esb, nsW, nsb, out);
}

// round 9
// speedup vs baseline: 1.3490x; 1.3447x over previous
#include <cuda_runtime.h>
#include <cuda_bf16.h>
#include <math.h>

#define NN 100000
#define EE 640000

// smem layout
#define AH_OFF 0
#define AL_OFF (16*1024)
#define BH_OFF (32*1024)
#define BL_OFF (48*1024)
#define EX_OFF (64*1024)
#define SMEM_BYTES (64*1024 + 2048)

// ---------------- device scratch ----------------
__device__ float g_node_h[(size_t)NN * 128];
__device__ float g_edge_h[(size_t)EE * 128];
__device__ float g_projA[(size_t)NN * 256];
__device__ float g_projB[(size_t)NN * 256];
__device__ float g_hbuf[(size_t)EE * 256];
__device__ float g_agg[(size_t)NN * 128];
__device__ float g_nh[(size_t)NN * 256];
__device__ float g_qvec[128];
__device__ float g_qc[3 * 256];

// transposed bf16 hi/lo weights: [L][C][K]
__device__ __align__(16) __nv_bfloat16 g_eW1t_h[3 * 256 * 512];
__device__ __align__(16) __nv_bfloat16 g_eW1t_l[3 * 256 * 512];
__device__ __align__(16) __nv_bfloat16 g_eW2t_h[3 * 128 * 256];
__device__ __align__(16) __nv_bfloat16 g_eW2t_l[3 * 128 * 256];
__device__ __align__(16) __nv_bfloat16 g_nW1t_h[3 * 256 * 256];
__device__ __align__(16) __nv_bfloat16 g_nW1t_l[3 * 256 * 256];
__device__ __align__(16) __nv_bfloat16 g_nW2t_h[3 * 128 * 256];
__device__ __align__(16) __nv_bfloat16 g_nW2t_l[3 * 128 * 256];

// ---------------- helpers ----------------
__device__ __forceinline__ unsigned smem_u32(const void* p) {
    unsigned a;
    asm("{ .reg .u64 t; cvta.to.shared.u64 t, %1; cvt.u32.u64 %0, t; }" : "=r"(a) : "l"(p));
    return a;
}

__device__ __forceinline__ void ldm_x4(unsigned* r, unsigned addr) {
    asm volatile("ldmatrix.sync.aligned.m8n8.x4.shared.b16 {%0,%1,%2,%3}, [%4];"
        : "=r"(r[0]), "=r"(r[1]), "=r"(r[2]), "=r"(r[3]) : "r"(addr));
}

__device__ __forceinline__ void mma_bf16(float* c, const unsigned* a, unsigned b0, unsigned b1) {
    asm volatile(
        "mma.sync.aligned.m16n8k16.row.col.f32.bf16.bf16.f32 "
        "{%0,%1,%2,%3}, {%4,%5,%6,%7}, {%8,%9}, {%0,%1,%2,%3};"
        : "+f"(c[0]), "+f"(c[1]), "+f"(c[2]), "+f"(c[3])
        : "r"(a[0]), "r"(a[1]), "r"(a[2]), "r"(a[3]), "r"(b0), "r"(b1));
}

// A: fp32 gmem [rows, pitch] -> smem hi/lo, 128 rows x 64 bf16, XOR-128B swizzle
__device__ __forceinline__ void load_a_split(const float* __restrict__ A, int pitch,
        int rowBase, int maxRow, int k0, char* smem, int tid) {
    int rl = tid >> 1;
    int r = rowBase + rl; if (r > maxRow) r = maxRow;
    int cbase = (tid & 1) * 32;
    const float* src = A + (size_t)r * pitch + k0 + cbase;
    #pragma unroll
    for (int j = 0; j < 8; j++) {
        float4 v = *(const float4*)(src + j * 4);
        __nv_bfloat16 h0 = __float2bfloat16_rn(v.x);
        __nv_bfloat16 h1 = __float2bfloat16_rn(v.y);
        __nv_bfloat16 h2 = __float2bfloat16_rn(v.z);
        __nv_bfloat16 h3 = __float2bfloat16_rn(v.w);
        unsigned hp0 = (unsigned)__bfloat16_as_ushort(h0) | ((unsigned)__bfloat16_as_ushort(h1) << 16);
        unsigned hp1 = (unsigned)__bfloat16_as_ushort(h2) | ((unsigned)__bfloat16_as_ushort(h3) << 16);
        __nv_bfloat16 l0 = __float2bfloat16_rn(v.x - __bfloat162float(h0));
        __nv_bfloat16 l1 = __float2bfloat16_rn(v.y - __bfloat162float(h1));
        __nv_bfloat16 l2 = __float2bfloat16_rn(v.z - __bfloat162float(h2));
        __nv_bfloat16 l3 = __float2bfloat16_rn(v.w - __bfloat162float(h3));
        unsigned lp0 = (unsigned)__bfloat16_as_ushort(l0) | ((unsigned)__bfloat16_as_ushort(l1) << 16);
        unsigned lp1 = (unsigned)__bfloat16_as_ushort(l2) | ((unsigned)__bfloat16_as_ushort(l3) << 16);
        int bo = rl * 128 + (cbase + j * 4) * 2;
        int sw = bo ^ ((bo >> 3) & 0x70);
        *(uint2*)(smem + AH_OFF + sw) = make_uint2(hp0, hp1);
        *(uint2*)(smem + AL_OFF + sw) = make_uint2(lp0, lp1);
    }
}

// B: bf16 hi/lo gmem [128 n-rows][Ktot] -> smem, 128 rows x 64 bf16, same swizzle
__device__ __forceinline__ void load_b_tiles(const __nv_bfloat16* __restrict__ Bh,
        const __nv_bfloat16* __restrict__ Bl, int Ktot, int k0, char* smem, int tid) {
    int rr = tid & 127;
    const __nv_bfloat16* src = ((tid < 128) ? Bh : Bl) + (size_t)rr * Ktot + k0;
    char* dst = smem + ((tid < 128) ? BH_OFF : BL_OFF);
    #pragma unroll
    for (int i = 0; i < 8; i++) {
        int4 x = *(const int4*)(src + i * 8);
        *(int4*)(dst + rr * 128 + ((i ^ (rr & 7)) << 4)) = x;
    }
}

// one 128-row x 128-col output pass, K = NCHUNK*64, 3-term bf16 split
template<int NCHUNK, bool SPLITSRC>
__device__ __forceinline__ void gemm_pass(const float* __restrict__ A0,
        const float* __restrict__ A1, int apitch, int rowBase, int maxRow,
        const __nv_bfloat16* __restrict__ BhT, const __nv_bfloat16* __restrict__ BlT,
        int bpitch, int bk0, char* smem, unsigned sbase, int tid, int lane,
        int Rw, int Cw, float (&acc)[2][8][4]) {
    #pragma unroll 1
    for (int kc = 0; kc < NCHUNK; kc++) {
        __syncthreads();
        const float* Ap = (SPLITSRC && kc >= 2) ? A1 : A0;
        int ak0 = SPLITSRC ? (kc & 1) * 64 : kc * 64;
        load_a_split(Ap, apitch, rowBase, maxRow, ak0, smem, tid);
        load_b_tiles(BhT, BlT, bpitch, bk0 + kc * 64, smem, tid);
        __syncthreads();
        int m = lane >> 3;
        #pragma unroll
        for (int ks = 0; ks < 4; ks++) {
            unsigned Ah[2][4], Al[2][4];
            #pragma unroll
            for (int mi = 0; mi < 2; mi++) {
                int row = Rw + mi * 16 + (lane & 7) + (m & 1) * 8;
                int kg = ks * 2 + (m >> 1);
                unsigned off = row * 128 + ((kg ^ (row & 7)) << 4);
                ldm_x4(Ah[mi], sbase + AH_OFF + off);
                ldm_x4(Al[mi], sbase + AL_OFF + off);
            }
            #pragma unroll
            for (int nh = 0; nh < 2; nh++) {
                unsigned Bh4[2][4], Bl4[2][4];
                #pragma unroll
                for (int q = 0; q < 2; q++) {
                    int n = Cw + nh * 32 + q * 16 + (m >> 1) * 8 + (lane & 7);
                    int kg = ks * 2 + (m & 1);
                    unsigned off = n * 128 + ((kg ^ (n & 7)) << 4);
                    ldm_x4(Bh4[q], sbase + BH_OFF + off);
                    ldm_x4(Bl4[q], sbase + BL_OFF + off);
                }
                #pragma unroll
                for (int mi = 0; mi < 2; mi++) {
                    #pragma unroll
                    for (int ni = 0; ni < 4; ni++) {
                        unsigned bh0 = Bh4[ni >> 1][(ni & 1) * 2];
                        unsigned bh1 = Bh4[ni >> 1][(ni & 1) * 2 + 1];
                        unsigned bl0 = Bl4[ni >> 1][(ni & 1) * 2];
                        unsigned bl1 = Bl4[ni >> 1][(ni & 1) * 2 + 1];
                        float* c = acc[mi][nh * 4 + ni];
                        mma_bf16(c, Ah[mi], bh0, bh1);
                        mma_bf16(c, Ah[mi], bl0, bl1);
                        mma_bf16(c, Al[mi], bh0, bh1);
                    }
                }
            }
        }
    }
}

#define ZERO_ACC(acc) { \
    _Pragma("unroll") for (int _i = 0; _i < 2; _i++) \
    _Pragma("unroll") for (int _j = 0; _j < 8; _j++) \
    _Pragma("unroll") for (int _k = 0; _k < 4; _k++) acc[_i][_j][_k] = 0.f; }

#define TILE_VARS() \
    extern __shared__ char smem[]; \
    unsigned sbase = smem_u32(smem); \
    int tid = threadIdx.x, lane = tid & 31, w = tid >> 5; \
    int Rw = (w & 3) * 32, Cw = (w >> 2) * 64; \
    int l4 = lane >> 2, l2 = (lane & 3) * 2;

// ---------------- small kernels ----------------
__global__ void k_qvec(const float* __restrict__ q, const float* __restrict__ qW,
                       const float* __restrict__ qb) {
    __shared__ float qs[768];
    int t = threadIdx.x;
    for (int i = t; i < 768; i += 128) qs[i] = q[i];
    __syncthreads();
    float s = qb[t];
    #pragma unroll 8
    for (int k = 0; k < 768; k++) s += qs[k] * qW[k * 128 + t];
    g_qvec[t] = s;
}

__global__ void k_qc(const float* __restrict__ eW1, const float* __restrict__ eb1) {
    __shared__ float qs[128];
    int l = blockIdx.x, t = threadIdx.x;
    if (t < 128) qs[t] = g_qvec[t];
    __syncthreads();
    const float* W = eW1 + ((size_t)l * 512 + 384) * 256;
    float s = eb1[l * 256 + t];
    #pragma unroll 8
    for (int k = 0; k < 128; k++) s += qs[k] * W[k * 256 + t];
    g_qc[l * 256 + t] = s;
}

// transpose + bf16 split: W [L][K][C] -> T [L][C][K]
__global__ void k_wprep(const float* __restrict__ W, __nv_bfloat16* __restrict__ Th,
                        __nv_bfloat16* __restrict__ Tl, int K, int C, int n) {
    int o = blockIdx.x * 256 + threadIdx.x;
    if (o >= n) return;
    int k = o % K;
    int c = (o / K) % C;
    int l = o / (K * C);
    float w = W[((size_t)l * K + k) * C + c];
    __nv_bfloat16 h = __float2bfloat16_rn(w);
    Th[o] = h;
    Tl[o] = __float2bfloat16_rn(w - __bfloat162float(h));
}

// ---------------- GEMM kernels ----------------
// proj: node_h[.,128] @ eW1[half*128:+128, 0:256] -> projA/projB
__global__ void __launch_bounds__(256) k_proj(const float* __restrict__ nsrc, int layer) {
    TILE_VARS();
    int rowBase = blockIdx.x * 128;
    int half = blockIdx.y;
    const __nv_bfloat16* BhT = g_eW1t_h + (size_t)layer * 256 * 512;
    const __nv_bfloat16* BlT = g_eW1t_l + (size_t)layer * 256 * 512;
    float* outp = half ? g_projB : g_projA;
    #pragma unroll 1
    for (int p = 0; p < 2; p++) {
        float acc[2][8][4];
        ZERO_ACC(acc);
        gemm_pass<2, false>(nsrc, nullptr, 128, rowBase, NN - 1,
            BhT + (size_t)p * 128 * 512, BlT + (size_t)p * 128 * 512, 512, half * 128,
            smem, sbase, tid, lane, Rw, Cw, acc);
        #pragma unroll
        for (int mi = 0; mi < 2; mi++)
        #pragma unroll
        for (int hf = 0; hf < 2; hf++) {
            int row = rowBase + Rw + mi * 16 + l4 + hf * 8;
            if (row < NN) {
                #pragma unroll
                for (int ni = 0; ni < 8; ni++) {
                    int col = p * 128 + Cw + ni * 8 + l2;
                    *(float2*)(outp + (size_t)row * 256 + col) =
                        make_float2(acc[mi][ni][hf * 2], acc[mi][ni][hf * 2 + 1]);
                }
            }
        }
    }
}

// e1: hbuf = relu(edge_h @ eW1[256:384] + projA[src] + projB[dst] + qc)
__global__ void __launch_bounds__(256) k_e1(const float* __restrict__ ehsrc,
                                            const int* __restrict__ eidx, int layer) {
    TILE_VARS();
    int rowBase = blockIdx.x * 128;
    int* ssm = (int*)(smem + EX_OFF);
    int* dsm = ssm + 128;
    if (tid < 128) { ssm[tid] = eidx[rowBase + tid]; dsm[tid] = eidx[EE + rowBase + tid]; }
    const __nv_bfloat16* BhT = g_eW1t_h + (size_t)layer * 256 * 512;
    const __nv_bfloat16* BlT = g_eW1t_l + (size_t)layer * 256 * 512;
    #pragma unroll 1
    for (int p = 0; p < 2; p++) {
        float acc[2][8][4];
        ZERO_ACC(acc);
        gemm_pass<2, false>(ehsrc, nullptr, 128, rowBase, EE - 1,
            BhT + (size_t)p * 128 * 512, BlT + (size_t)p * 128 * 512, 512, 256,
            smem, sbase, tid, lane, Rw, Cw, acc);
        #pragma unroll
        for (int mi = 0; mi < 2; mi++)
        #pragma unroll
        for (int hf = 0; hf < 2; hf++) {
            int rl = Rw + mi * 16 + l4 + hf * 8;
            int row = rowBase + rl;
            int s = ssm[rl], d = dsm[rl];
            #pragma unroll
            for (int ni = 0; ni < 8; ni++) {
                int col = p * 128 + Cw + ni * 8 + l2;
                float2 pa = *(const float2*)(g_projA + (size_t)s * 256 + col);
                float2 pb = *(const float2*)(g_projB + (size_t)d * 256 + col);
                float2 qv = *(const float2*)(g_qc + layer * 256 + col);
                float v0 = fmaxf(acc[mi][ni][hf * 2 + 0] + pa.x + pb.x + qv.x, 0.f);
                float v1 = fmaxf(acc[mi][ni][hf * 2 + 1] + pa.y + pb.y + qv.y, 0.f);
                *(float2*)(g_hbuf + (size_t)row * 256 + col) = make_float2(v0, v1);
            }
        }
    }
}

// e2: edge_h = hbuf @ eW2 + eb2 ; atomic scatter-add into agg[src], agg[dst]
__global__ void __launch_bounds__(256) k_e2(const int* __restrict__ eidx,
                                            const float* __restrict__ eb2l, int layer) {
    TILE_VARS();
    int rowBase = blockIdx.x * 128;
    int* ssm = (int*)(smem + EX_OFF);
    int* dsm = ssm + 128;
    if (tid < 128) { ssm[tid] = eidx[rowBase + tid]; dsm[tid] = eidx[EE + rowBase + tid]; }
    const __nv_bfloat16* BhT = g_eW2t_h + (size_t)layer * 128 * 256;
    const __nv_bfloat16* BlT = g_eW2t_l + (size_t)layer * 128 * 256;
    float acc[2][8][4];
    ZERO_ACC(acc);
    gemm_pass<4, false>(g_hbuf, nullptr, 256, rowBase, EE - 1,
        BhT, BlT, 256, 0, smem, sbase, tid, lane, Rw, Cw, acc);
    #pragma unroll
    for (int mi = 0; mi < 2; mi++)
    #pragma unroll
    for (int hf = 0; hf < 2; hf++) {
        int rl = Rw + mi * 16 + l4 + hf * 8;
        int row = rowBase + rl;
        int s = ssm[rl], d = dsm[rl];
        #pragma unroll
        for (int ni = 0; ni < 8; ni++) {
            int col = Cw + ni * 8 + l2;
            float2 bb = *(const float2*)(eb2l + col);
            float v0 = acc[mi][ni][hf * 2 + 0] + bb.x;
            float v1 = acc[mi][ni][hf * 2 + 1] + bb.y;
            *(float2*)(g_edge_h + (size_t)row * 128 + col) = make_float2(v0, v1);
            atomicAdd(g_agg + (size_t)s * 128 + col + 0, v0);
            atomicAdd(g_agg + (size_t)s * 128 + col + 1, v1);
            atomicAdd(g_agg + (size_t)d * 128 + col + 0, v0);
            atomicAdd(g_agg + (size_t)d * 128 + col + 1, v1);
        }
    }
}

// n1: nh = relu([node_h | agg] @ nW1 + nb1)
__global__ void __launch_bounds__(256) k_n1(const float* __restrict__ nsrc,
                                            const float* __restrict__ nb1, int layer) {
    TILE_VARS();
    int rowBase = blockIdx.x * 128;
    const __nv_bfloat16* BhT = g_nW1t_h + (size_t)layer * 256 * 256;
    const __nv_bfloat16* BlT = g_nW1t_l + (size_t)layer * 256 * 256;
    #pragma unroll 1
    for (int p = 0; p < 2; p++) {
        float acc[2][8][4];
        ZERO_ACC(acc);
        gemm_pass<4, true>(nsrc, g_agg, 128, rowBase, NN - 1,
            BhT + (size_t)p * 128 * 256, BlT + (size_t)p * 128 * 256, 256, 0,
            smem, sbase, tid, lane, Rw, Cw, acc);
        #pragma unroll
        for (int mi = 0; mi < 2; mi++)
        #pragma unroll
        for (int hf = 0; hf < 2; hf++) {
            int row = rowBase + Rw + mi * 16 + l4 + hf * 8;
            if (row < NN) {
                #pragma unroll
                for (int ni = 0; ni < 8; ni++) {
                    int col = p * 128 + Cw + ni * 8 + l2;
                    float2 bb = *(const float2*)(nb1 + layer * 256 + col);
                    float v0 = fmaxf(acc[mi][ni][hf * 2 + 0] + bb.x, 0.f);
                    float v1 = fmaxf(acc[mi][ni][hf * 2 + 1] + bb.y, 0.f);
                    *(float2*)(g_nh + (size_t)row * 256 + col) = make_float2(v0, v1);
                }
            }
        }
    }
}

// n2: node_h = nh @ nW2 + nb2
__global__ void __launch_bounds__(256) k_n2(const float* __restrict__ nb2l, int layer) {
    TILE_VARS();
    int rowBase = blockIdx.x * 128;
    const __nv_bfloat16* BhT = g_nW2t_h + (size_t)layer * 128 * 256;
    const __nv_bfloat16* BlT = g_nW2t_l + (size_t)layer * 128 * 256;
    float acc[2][8][4];
    ZERO_ACC(acc);
    gemm_pass<4, false>(g_nh, nullptr, 256, rowBase, NN - 1,
        BhT, BlT, 256, 0, smem, sbase, tid, lane, Rw, Cw, acc);
    #pragma unroll
    for (int mi = 0; mi < 2; mi++)
    #pragma unroll
    for (int hf = 0; hf < 2; hf++) {
        int row = rowBase + Rw + mi * 16 + l4 + hf * 8;
        if (row < NN) {
            #pragma unroll
            for (int ni = 0; ni < 8; ni++) {
                int col = Cw + ni * 8 + l2;
                float2 bb = *(const float2*)(nb2l + col);
                *(float2*)(g_node_h + (size_t)row * 128 + col) = make_float2(
                    acc[mi][ni][hf * 2 + 0] + bb.x, acc[mi][ni][hf * 2 + 1] + bb.y);
            }
        }
    }
}

// scores
__global__ void k_scores(const float* __restrict__ esW, const float* __restrict__ esb,
                         const float* __restrict__ nsW, const float* __restrict__ nsb,
                         float* __restrict__ out) {
    int warp = (blockIdx.x * blockDim.x + threadIdx.x) >> 5;
    int lane = threadIdx.x & 31;
    if (warp >= NN + EE) return;
    const float* row; const float* w; float b;
    if (warp < NN) { row = g_node_h + (size_t)warp * 128; w = nsW; b = nsb[0]; }
    else           { row = g_edge_h + (size_t)(warp - NN) * 128; w = esW; b = esb[0]; }
    float4 v = ((const float4*)row)[lane];
    float4 wv = ((const float4*)w)[lane];
    float s = v.x * wv.x + v.y * wv.y + v.z * wv.z + v.w * wv.w;
    #pragma unroll
    for (int off = 16; off > 0; off >>= 1) s += __shfl_xor_sync(0xffffffffu, s, off);
    if (lane == 0) out[warp] = 1.f / (1.f + expf(-(s + b)));
}

// ---------------- host ----------------
extern "C" void kernel_launch(void* const* d_in, const int* in_sizes, int n_in,
                              void* d_out, int out_size) {
    const float* node_emb = (const float*)d_in[0];
    const float* rel_emb  = (const float*)d_in[1];
    const float* q_emb    = (const float*)d_in[2];
    const int*   eidx     = (const int*)d_in[3];
    const float* qW  = (const float*)d_in[5];
    const float* qb  = (const float*)d_in[6];
    const float* eW1 = (const float*)d_in[7];
    const float* eb1 = (const float*)d_in[8];
    const float* eW2 = (const float*)d_in[9];
    const float* eb2 = (const float*)d_in[10];
    const float* nW1 = (const float*)d_in[11];
    const float* nb1 = (const float*)d_in[12];
    const float* nW2 = (const float*)d_in[13];
    const float* nb2 = (const float*)d_in[14];
    const float* esW = (const float*)d_in[15];
    const float* esb = (const float*)d_in[16];
    const float* nsW = (const float*)d_in[17];
    const float* nsb = (const float*)d_in[18];
    float* out = (float*)d_out;

    cudaFuncSetAttribute(k_proj, cudaFuncAttributeMaxDynamicSharedMemorySize, SMEM_BYTES);
    cudaFuncSetAttribute(k_e1,   cudaFuncAttributeMaxDynamicSharedMemorySize, SMEM_BYTES);
    cudaFuncSetAttribute(k_e2,   cudaFuncAttributeMaxDynamicSharedMemorySize, SMEM_BYTES);
    cudaFuncSetAttribute(k_n1,   cudaFuncAttributeMaxDynamicSharedMemorySize, SMEM_BYTES);
    cudaFuncSetAttribute(k_n2,   cudaFuncAttributeMaxDynamicSharedMemorySize, SMEM_BYTES);

    void *aggPtr = nullptr, *nodeHPtr = nullptr, *edgeHPtr = nullptr;
    void *w1h, *w1l, *w2h, *w2l, *n1h, *n1l, *n2h, *n2l;
    cudaGetSymbolAddress(&aggPtr, g_agg);
    cudaGetSymbolAddress(&nodeHPtr, g_node_h);
    cudaGetSymbolAddress(&edgeHPtr, g_edge_h);
    cudaGetSymbolAddress(&w1h, g_eW1t_h); cudaGetSymbolAddress(&w1l, g_eW1t_l);
    cudaGetSymbolAddress(&w2h, g_eW2t_h); cudaGetSymbolAddress(&w2l, g_eW2t_l);
    cudaGetSymbolAddress(&n1h, g_nW1t_h); cudaGetSymbolAddress(&n1l, g_nW1t_l);
    cudaGetSymbolAddress(&n2h, g_nW2t_h); cudaGetSymbolAddress(&n2l, g_nW2t_l);

    {
        int n;
        n = 3 * 512 * 256;
        k_wprep<<<(n + 255) / 256, 256>>>(eW1, (__nv_bfloat16*)w1h, (__nv_bfloat16*)w1l, 512, 256, n);
        n = 3 * 256 * 128;
        k_wprep<<<(n + 255) / 256, 256>>>(eW2, (__nv_bfloat16*)w2h, (__nv_bfloat16*)w2l, 256, 128, n);
        n = 3 * 256 * 256;
        k_wprep<<<(n + 255) / 256, 256>>>(nW1, (__nv_bfloat16*)n1h, (__nv_bfloat16*)n1l, 256, 256, n);
        n = 3 * 256 * 128;
        k_wprep<<<(n + 255) / 256, 256>>>(nW2, (__nv_bfloat16*)n2h, (__nv_bfloat16*)n2l, 256, 128, n);
    }

    k_qvec<<<1, 128>>>(q_emb, qW, qb);
    k_qc<<<3, 256>>>(eW1, eb1);

    const int NBT = (NN + 127) / 128;  // 782
    const int EBT = EE / 128;          // 5000

    const float* nh_src = node_emb;
    const float* eh_src = rel_emb;
    for (int l = 0; l < 3; l++) {
        k_proj<<<dim3(NBT, 2), 256, SMEM_BYTES>>>(nh_src, l);
        k_e1<<<EBT, 256, SMEM_BYTES>>>(eh_src, eidx, l);
        cudaMemsetAsync(aggPtr, 0, (size_t)NN * 128 * sizeof(float));
        k_e2<<<EBT, 256, SMEM_BYTES>>>(eidx, eb2 + l * 128, l);
        k_n1<<<NBT, 256, SMEM_BYTES>>>(nh_src, nb1, l);
        k_n2<<<NBT, 256, SMEM_BYTES>>>(nb2 + l * 128, l);
        nh_src = (const float*)nodeHPtr;
        eh_src = (const float*)edgeHPtr;
    }

    int totalWarps = NN + EE;
    int blocks = (totalWarps + 7) / 8;
    k_scores<<<blocks, 256>>>(esW, esb, nsW, nsb, out);
}